// round 2
// baseline (speedup 1.0000x reference)
#include <cuda_runtime.h>
#include <cstdint>
#include <cstddef>

// ============================================================================
// AlignToZWignerD: D^l (l=0..4) Wigner blocks for real spherical harmonics,
// Ivanic-Ruedenberg recurrence. Output (N, 25, 25) fp32, block-diagonal.
// ============================================================================

#define NT 64            // threads (= points) per block
#define COMPACT 165      // 1 + 9 + 25 + 49 + 81
#define NENT 155         // recurrence entries for l=2..4 (25+49+81)

// ---------------- compile-time sqrt (Newton, double) ----------------
constexpr double csqrt_(double x) {
    if (x <= 0.0) return 0.0;
    double r = x > 1.0 ? x : 1.0;
    for (int i = 0; i < 100; i++) r = 0.5 * (r + x / r);
    return r;
}

// ---------------- compile-time u,v,w coefficient table ----------------
// One float4 (u, v, w, 0) per (l, m, mp) entry, loop order l, m, mp.
struct alignas(16) UvwT { float v[NENT * 4]; };

constexpr UvwT make_uvw() {
    UvwT t{};
    int e = 0;
    for (int l = 2; l <= 4; l++) {
        for (int m = -l; m <= l; m++) {
            for (int mp = -l; mp <= l; mp++) {
                double denom = (mp == l || mp == -l)
                                   ? double((2 * l) * (2 * l - 1))
                                   : double((l + mp) * (l - mp));
                int am = m < 0 ? -m : m;
                double d0 = (m == 0) ? 1.0 : 0.0;
                double u = csqrt_(double((l + m) * (l - m)) / denom);
                double v = 0.5 * csqrt_((1.0 + d0) * double((l + am - 1) * (l + am)) / denom)
                           * (1.0 - 2.0 * d0);
                int wn = l - am - 1; if (wn < 0) wn = 0;
                double w = -0.5 * csqrt_(double(wn * (l - am)) / denom) * (1.0 - d0);
                t.v[e * 4 + 0] = (float)u;
                t.v[e * 4 + 1] = (float)v;
                t.v[e * 4 + 2] = (float)w;
                t.v[e * 4 + 3] = 0.0f;
                e++;
            }
        }
    }
    return t;
}

__device__ const UvwT G_UVW = make_uvw();

// ---------------- compile-time output map: 625 -> compact idx or -1 ----------
struct CmapT { short v[640]; };

constexpr CmapT make_cmap() {
    CmapT c{};
    for (int j = 0; j < 640; j++) c.v[j] = -1;
    for (int j = 0; j < 625; j++) {
        int r = j / 25, cc = j % 25;
        int l = 0;
        while ((l + 1) * (l + 1) <= r) l++;
        int lo = l * l, hi = (l + 1) * (l + 1);
        if (cc >= lo && cc < hi) {
            int base = l * (2 * l - 1) * (2 * l + 1) / 3;  // 0,1,10,35,84
            c.v[j] = (short)(base + (r - lo) * (2 * l + 1) + (cc - lo));
        } else {
            c.v[j] = -1;
        }
    }
    return c;
}

__device__ const CmapT G_CMAP = make_cmap();

// ---------------- P accumulation (Ivanic-Ruedenberg helper) ----------------
// r1: 9 floats (flattened 3x3 D^1 in SH basis), dp: D^{l-1} flattened (np x np)
__device__ __forceinline__ float Pacc(int i, int a, int b, int l, int lp, int np,
                                      const float* __restrict__ r1,
                                      const float* __restrict__ dp) {
    int row = (i + 1) * 3;
    if (b == l)
        return r1[row + 2] * dp[(a + lp) * np + 2 * lp] - r1[row + 0] * dp[(a + lp) * np + 0];
    if (b == -l)
        return r1[row + 2] * dp[(a + lp) * np + 0] + r1[row + 0] * dp[(a + lp) * np + 2 * lp];
    return r1[row + 1] * dp[(a + lp) * np + (b + lp)];
}

// ---------------- main kernel ----------------
__global__ void AlignToZWignerD_kernel(const float* __restrict__ xyz,
                                       float* __restrict__ out, int N) {
    extern __shared__ float sm[];   // NT * COMPACT floats
    const int tid = threadIdx.x;
    const int p   = blockIdx.x * NT + tid;
    float* row = sm + tid * COMPACT;

    if (p < N) {
        // --- geometry ---
        float x = xyz[3 * p + 0], y = xyz[3 * p + 1], z = xyz[3 * p + 2];
        float nrm = sqrtf(x * x + y * y + z * z);
        float inv = 1.0f / fmaxf(nrm, 1e-14f);
        float vx = x * inv, vy = y * inv, vz = z * inv;
        float ct = fminf(1.0f, fmaxf(-1.0f, vz));
        float st = sqrtf(fmaxf(0.0f, 1.0f - ct * ct));
        float rxy = sqrtf(vx * vx + vy * vy);
        float cp, sp;
        if (rxy > 0.0f) { float ir = 1.0f / rxy; cp = vx * ir; sp = vy * ir; }
        else            { cp = 1.0f; sp = 0.0f; }

        // --- D^0 and D^1 (SH basis: rows/cols permuted by p=[1,2,0]) ---
        row[0] = 1.0f;
        row[1] = cp;       row[2] = 0.0f;  row[3] = -sp;
        row[4] = st * sp;  row[5] = ct;    row[6] = st * cp;
        row[7] = ct * sp;  row[8] = -st;   row[9] = ct * cp;

        const float* r1 = row + 1;
        const float4* UVW = reinterpret_cast<const float4*>(G_UVW.v);

        int e = 0, prev = 1, cur = 10;
        #pragma unroll
        for (int l = 2; l <= 4; l++) {
            const int n = 2 * l + 1, lp = l - 1, np = 2 * l - 1;
            const float* dp = row + prev;
            float* dl = row + cur;
            for (int m = -l; m <= l; m++) {
                for (int mp = -l; mp <= l; mp++) {
                    float4 q = UVW[e]; e++;
                    float acc = 0.0f;
                    if (m > -l && m < l)
                        acc += q.x * Pacc(0, m, mp, l, lp, np, r1, dp);
                    if (m == 0) {
                        acc += q.y * (Pacc(1, 1, mp, l, lp, np, r1, dp)
                                    + Pacc(-1, -1, mp, l, lp, np, r1, dp));
                    } else if (m > 0) {
                        float s = (m == 1) ? 1.4142135623730951f : 1.0f;
                        acc += q.y * s * Pacc(1, m - 1, mp, l, lp, np, r1, dp);
                        if (m != 1)
                            acc -= q.y * Pacc(-1, -m + 1, mp, l, lp, np, r1, dp);
                    } else {
                        if (m != -1)
                            acc += q.y * Pacc(1, m + 1, mp, l, lp, np, r1, dp);
                        float s = (m == -1) ? 1.4142135623730951f : 1.0f;
                        acc += q.y * s * Pacc(-1, -m - 1, mp, l, lp, np, r1, dp);
                    }
                    if (m != 0 && m <= l - 2 && m >= -(l - 2)) {
                        if (m > 0)
                            acc += q.z * (Pacc(1, m + 1, mp, l, lp, np, r1, dp)
                                        + Pacc(-1, -m - 1, mp, l, lp, np, r1, dp));
                        else
                            acc += q.z * (Pacc(1, m - 1, mp, l, lp, np, r1, dp)
                                        - Pacc(-1, -m + 1, mp, l, lp, np, r1, dp));
                    }
                    dl[(m + l) * n + (mp + l)] = acc;
                }
            }
            prev = cur; cur += n * n;
        }
    }

    __syncthreads();

    // --- coalesced write-out: each warp streams one point's 625-float row ---
    const int lane = tid & 31, warp = tid >> 5;
    const int p0 = blockIdx.x * NT;
    const short* cm = G_CMAP.v;
    for (int pt = warp; pt < NT; pt += NT / 32) {
        int pp = p0 + pt;
        if (pp >= N) break;
        const float* r = sm + pt * COMPACT;
        float* o = out + (size_t)pp * 625;
        #pragma unroll 5
        for (int j = lane; j < 625; j += 32) {
            int mi = cm[j];
            o[j] = (mi >= 0) ? r[mi] : 0.0f;
        }
    }
}

// ---------------- launch ----------------
extern "C" void kernel_launch(void* const* d_in, const int* in_sizes, int n_in,
                              void* d_out, int out_size) {
    const float* xyz = (const float*)d_in[0];
    float* out = (float*)d_out;
    int N = in_sizes[0] / 3;
    int grid = (N + NT - 1) / NT;
    AlignToZWignerD_kernel<<<grid, NT, NT * COMPACT * sizeof(float)>>>(xyz, out, N);
}

// round 7
// speedup vs baseline: 4.4892x; 4.4892x over previous
#include <cuda_runtime.h>
#include <cstdint>
#include <cstddef>

// ============================================================================
// AlignToZWignerD: D^l (l=0..4) Wigner blocks for real spherical harmonics,
// Ivanic-Ruedenberg recurrence, fully unrolled at compile time.
// Output (N, 25, 25) fp32, block-diagonal. N = 200000.
// ============================================================================

#define COMPACT 165       // 1 + 9 + 25 + 49 + 81
#define ROWSTRIDE 167     // pad: gcd(167,32)=1 -> conflict-free; slot 165 = 0.0f

// ---------------- compile-time sqrt (Newton, double) ----------------
constexpr __host__ __device__ double csqrt_(double x) {
    if (x <= 0.0) return 0.0;
    double r = x > 1.0 ? x : 1.0;
    for (int i = 0; i < 60; i++) r = 0.5 * (r + x / r);
    return r;
}

// ---------------- compile-time u, v, w coefficients ----------------
constexpr __host__ __device__ double denom_(int l, int mp) {
    return (mp == l || mp == -l) ? double((2 * l) * (2 * l - 1))
                                 : double((l + mp) * (l - mp));
}
constexpr __host__ __device__ double u_of(int l, int m, int mp) {
    return csqrt_(double((l + m) * (l - m)) / denom_(l, mp));
}
constexpr __host__ __device__ double v_of(int l, int m, int mp) {
    int am = m < 0 ? -m : m;
    double d0 = (m == 0) ? 1.0 : 0.0;
    return 0.5 * csqrt_((1.0 + d0) * double((l + am - 1) * (l + am)) / denom_(l, mp))
           * (1.0 - 2.0 * d0);
}
constexpr __host__ __device__ double w_of(int l, int m, int mp) {
    int am = m < 0 ? -m : m;
    double d0 = (m == 0) ? 1.0 : 0.0;
    int wn = l - am - 1; if (wn < 0) wn = 0;
    return -0.5 * csqrt_(double(wn * (l - am)) / denom_(l, mp)) * (1.0 - d0);
}

// ---------------- integer sequence (self-contained) ----------------
template <int... Is> struct ISeq {};
template <int N, int... Is> struct MkSeq : MkSeq<N - 1, N - 1, Is...> {};
template <int... Is> struct MkSeq<0, Is...> { using type = ISeq<Is...>; };

// ---------------- P term (all indices compile-time) ----------------
template <int L, int I, int A, int B>
__device__ __forceinline__ float Pt(const float (&r1)[9],
                                    const float (&dp)[(2 * L - 1) * (2 * L - 1)]) {
    constexpr int lp = L - 1, np = 2 * L - 1, row = (I + 1) * 3;
    if constexpr (B == L)
        return r1[row + 2] * dp[(A + lp) * np + 2 * lp]
             - r1[row + 0] * dp[(A + lp) * np + 0];
    else if constexpr (B == -L)
        return r1[row + 2] * dp[(A + lp) * np + 0]
             + r1[row + 0] * dp[(A + lp) * np + 2 * lp];
    else
        return r1[row + 1] * dp[(A + lp) * np + (B + lp)];
}

// ---------------- one D^L entry (coefficients are immediates) ----------------
template <int L, int M, int MP>
__device__ __forceinline__ float entry(const float (&r1)[9],
                                       const float (&dp)[(2 * L - 1) * (2 * L - 1)]) {
    constexpr float u = (float)u_of(L, M, MP);
    constexpr float v = (float)v_of(L, M, MP);
    constexpr float w = (float)w_of(L, M, MP);
    constexpr float SQ2 = 1.41421356237309515f;
    float acc = 0.0f;
    if constexpr (u != 0.0f)
        acc += u * Pt<L, 0, M, MP>(r1, dp);
    if constexpr (v != 0.0f) {
        if constexpr (M == 0) {
            acc += v * (Pt<L, 1, 1, MP>(r1, dp) + Pt<L, -1, -1, MP>(r1, dp));
        } else if constexpr (M > 0) {
            constexpr float s = (M == 1) ? SQ2 : 1.0f;
            acc += (v * s) * Pt<L, 1, M - 1, MP>(r1, dp);
            if constexpr (M != 1)
                acc -= v * Pt<L, -1, -M + 1, MP>(r1, dp);
        } else {
            if constexpr (M != -1)
                acc += v * Pt<L, 1, M + 1, MP>(r1, dp);
            constexpr float s = (M == -1) ? SQ2 : 1.0f;
            acc += (v * s) * Pt<L, -1, -M - 1, MP>(r1, dp);
        }
    }
    if constexpr (w != 0.0f) {
        if constexpr (M > 0)
            acc += w * (Pt<L, 1, M + 1, MP>(r1, dp) + Pt<L, -1, -M - 1, MP>(r1, dp));
        else
            acc += w * (Pt<L, 1, M - 1, MP>(r1, dp) - Pt<L, -1, -M + 1, MP>(r1, dp));
    }
    return acc;
}

// ---------------- build D^L into registers / into smem ----------------
template <int L, int... Is>
__device__ __forceinline__ void build_reg_impl(const float (&r1)[9],
                                               const float (&dp)[(2 * L - 1) * (2 * L - 1)],
                                               float (&dl)[(2 * L + 1) * (2 * L + 1)],
                                               ISeq<Is...>) {
    ((dl[Is] = entry<L, Is / (2 * L + 1) - L, Is % (2 * L + 1) - L>(r1, dp)), ...);
}
template <int L>
__device__ __forceinline__ void build_reg(const float (&r1)[9],
                                          const float (&dp)[(2 * L - 1) * (2 * L - 1)],
                                          float (&dl)[(2 * L + 1) * (2 * L + 1)]) {
    build_reg_impl<L>(r1, dp, dl, typename MkSeq<(2 * L + 1) * (2 * L + 1)>::type{});
}

template <int L, int... Is>
__device__ __forceinline__ void build_smem_impl(const float (&r1)[9],
                                                const float (&dp)[(2 * L - 1) * (2 * L - 1)],
                                                float* __restrict__ srow, ISeq<Is...>) {
    ((srow[Is] = entry<L, Is / (2 * L + 1) - L, Is % (2 * L + 1) - L>(r1, dp)), ...);
}
template <int L>
__device__ __forceinline__ void build_smem(const float (&r1)[9],
                                           const float (&dp)[(2 * L - 1) * (2 * L - 1)],
                                           float* __restrict__ srow) {
    build_smem_impl<L>(r1, dp, srow, typename MkSeq<(2 * L + 1) * (2 * L + 1)>::type{});
}

// ---------------- output map: 625 -> compact idx, pad -> zero slot 165 -------
struct CmapT { short v[640]; };
constexpr __host__ __device__ CmapT make_cmap() {
    CmapT c{};
    for (int j = 0; j < 640; j++) c.v[j] = COMPACT;   // zero slot
    for (int j = 0; j < 625; j++) {
        int r = j / 25, cc = j % 25;
        int l = 0;
        while ((l + 1) * (l + 1) <= r) l++;
        int lo = l * l, hi = (l + 1) * (l + 1);
        if (cc >= lo && cc < hi) {
            int base = l * (2 * l - 1) * (2 * l + 1) / 3;   // 0,1,10,35,84
            c.v[j] = (short)(base + (r - lo) * (2 * l + 1) + (cc - lo));
        }
    }
    return c;
}
__device__ const CmapT G_CMAP = make_cmap();

// ---------------- main kernel: one warp per CTA, 32 points ----------------
__global__ void __launch_bounds__(32, 10)
AlignToZWignerD_kernel(const float* __restrict__ xyz, float* __restrict__ out, int N) {
    __shared__ float sm[32 * ROWSTRIDE];
    const int lane = threadIdx.x;
    const int p = blockIdx.x * 32 + lane;
    float* row = sm + lane * ROWSTRIDE;

    if (p < N) {
        // --- geometry ---
        float x = xyz[3 * p + 0], y = xyz[3 * p + 1], z = xyz[3 * p + 2];
        float nrm = sqrtf(x * x + y * y + z * z);
        float inv = 1.0f / fmaxf(nrm, 1e-14f);
        float vx = x * inv, vy = y * inv, vz = z * inv;
        float ct = fminf(1.0f, fmaxf(-1.0f, vz));
        float st = sqrtf(fmaxf(0.0f, 1.0f - ct * ct));
        float rxy = sqrtf(vx * vx + vy * vy);
        float cp, sp;
        if (rxy > 0.0f) { float ir = 1.0f / rxy; cp = vx * ir; sp = vy * ir; }
        else            { cp = 1.0f; sp = 0.0f; }

        // D^1 in real-SH basis (rows/cols permuted by p=[1,2,0])
        float r1[9] = { cp,      0.0f, -sp,
                        st * sp, ct,    st * cp,
                        ct * sp, -st,   ct * cp };

        row[0] = 1.0f;
        #pragma unroll
        for (int i = 0; i < 9; i++) row[1 + i] = r1[i];

        float d2[25];
        build_reg<2>(r1, r1, d2);
        #pragma unroll
        for (int i = 0; i < 25; i++) row[10 + i] = d2[i];

        float d3[49];
        build_reg<3>(r1, d2, d3);
        #pragma unroll
        for (int i = 0; i < 49; i++) row[35 + i] = d3[i];

        build_smem<4>(r1, d3, row + 84);     // 81 entries straight to smem

        row[COMPACT] = 0.0f;                  // zero slot
    }
    __syncwarp();

    // --- write-out: warp streams all 32 points' 625-float rows (coalesced) ---
    // hoist the 20 map values (depend only on lane) out of the point loop
    int mi[20];
    #pragma unroll
    for (int it = 0; it < 20; it++) {
        int j = it * 32 + lane;
        mi[it] = (j < 625) ? (int)G_CMAP.v[j] : COMPACT;
    }

    const int blk0 = blockIdx.x * 32;
    #pragma unroll 2
    for (int pt = 0; pt < 32; pt++) {
        int pp = blk0 + pt;
        if (pp >= N) break;
        const float* r = sm + pt * ROWSTRIDE;
        float* o = out + (size_t)pp * 625;
        #pragma unroll
        for (int it = 0; it < 20; it++) {
            int j = it * 32 + lane;
            if (j < 625) o[j] = r[mi[it]];
        }
    }
}

// ---------------- launch ----------------
extern "C" void kernel_launch(void* const* d_in, const int* in_sizes, int n_in,
                              void* d_out, int out_size) {
    const float* xyz = (const float*)d_in[0];
    float* out = (float*)d_out;
    int N = in_sizes[0] / 3;
    int grid = (N + 31) / 32;
    AlignToZWignerD_kernel<<<grid, 32>>>(xyz, out, N);
}